// round 2
// baseline (speedup 1.0000x reference)
#include <cuda_runtime.h>

#define NNODES 20000
#define NEDGES 640000
#define RREL 64
#define BBASIS 16
#define DIN 128
#define DOUT 128
#define KG (BBASIS * DIN)   /* 2048 */
#define KTOT (KG + DIN)     /* 2176 */

typedef unsigned long long ull;

__device__ __forceinline__ ull f2fma(ull a, ull b, ull c) {
    ull d;
    asm("fma.rn.f32x2 %0, %1, %2, %3;" : "=l"(d) : "l"(a), "l"(b), "l"(c));
    return d;
}
__device__ __forceinline__ ull f2dup(float v) {
    ull d; asm("mov.b64 %0, {%1, %1};" : "=l"(d) : "f"(v)); return d;
}
__device__ __forceinline__ float f2lo(ull v) { return __uint_as_float((unsigned)v); }
__device__ __forceinline__ float f2hi(ull v) { return __uint_as_float((unsigned)(v >> 32)); }

// Scratch (static device globals -- no allocation in kernel_launch)
__device__ float g_G[(size_t)NNODES * KG];   // [N][B][IN]
__device__ int g_cnt[NNODES];
__device__ int g_cur[NNODES];
__device__ int g_off[NNODES + 1];
__device__ int g_perm[NEDGES];

// ---------------- counting sort by dst ----------------

__global__ void k_init(int n) {
    int i = blockIdx.x * blockDim.x + threadIdx.x;
    if (i < n) { g_cnt[i] = 0; g_cur[i] = 0; }
}

__global__ void k_hist(const int* __restrict__ dst, int e) {
    int i = blockIdx.x * blockDim.x + threadIdx.x;
    if (i < e) atomicAdd(&g_cnt[dst[i]], 1);
}

__global__ void k_scan(int n) {
    __shared__ int sums[1024];
    int t = threadIdx.x;
    const int chunk = (n + 1023) / 1024;
    int base = t * chunk;
    int s = 0;
    for (int j = 0; j < chunk; j++) {
        int idx = base + j;
        if (idx < n) s += g_cnt[idx];
    }
    sums[t] = s;
    __syncthreads();
    for (int d = 1; d < 1024; d <<= 1) {
        int v = (t >= d) ? sums[t - d] : 0;
        __syncthreads();
        sums[t] += v;
        __syncthreads();
    }
    int run = (t == 0) ? 0 : sums[t - 1];
    for (int j = 0; j < chunk; j++) {
        int idx = base + j;
        if (idx < n) { g_off[idx] = run; run += g_cnt[idx]; }
    }
    if (t == 1023) g_off[n] = run;
}

__global__ void k_scatter(const int* __restrict__ dst, int e) {
    int i = blockIdx.x * blockDim.x + threadIdx.x;
    if (i < e) {
        int d = dst[i];
        int p = g_off[d] + atomicAdd(&g_cur[d], 1);
        g_perm[p] = i;
    }
}

// ---------------- edge accumulation ----------------
// One block per dst node, 128 threads. Thread t owns x-column t and keeps all
// 16 basis accumulators in registers (as 8 f32x2 pairs). The x row is read
// from L2 EXACTLY ONCE per edge (coalesced 512B). w_comp row is an LDS.128
// broadcast.

__global__ void __launch_bounds__(128) k_edge(
    const float* __restrict__ x, const float* __restrict__ wcomp,
    const float* __restrict__ norm, const int* __restrict__ src,
    const int* __restrict__ et)
{
    __shared__ float wc_s[RREL * BBASIS];
    int t = threadIdx.x;
#pragma unroll
    for (int j = 0; j < 8; j++) wc_s[t + j * 128] = wcomp[t + j * 128];
    __syncthreads();

    int d = blockIdx.x;
    ull acc[8];
#pragma unroll
    for (int j = 0; j < 8; j++) acc[j] = 0ull;

    int k0 = g_off[d], k1 = g_off[d + 1];

    int s = 0, r = 0; float nv = 0.f;
    if (k0 < k1) {
        int e = g_perm[k0];
        s = src[e]; r = et[e]; nv = norm[e];
    }
    for (int k = k0; k < k1; k++) {
        int cs = s, cr = r; float cn = nv;
        if (k + 1 < k1) {
            int e = g_perm[k + 1];
            s = src[e]; r = et[e]; nv = norm[e];
        }
        float xv = __ldg(x + (size_t)cs * DIN + t) * cn;
        ull xd = f2dup(xv);
        const ull* wp = (const ull*)&wc_s[cr << 4];
#pragma unroll
        for (int j = 0; j < 8; j++) acc[j] = f2fma(wp[j], xd, acc[j]);
    }

    float* gp = g_G + (size_t)d * KG + t;
#pragma unroll
    for (int j = 0; j < 8; j++) {
        gp[(2 * j) * DIN]     = f2lo(acc[j]);
        gp[(2 * j + 1) * DIN] = f2hi(acc[j]);
    }
}

// ---------------- fused GEMM with packed f32x2 FMA ----------------
// out = relu([G | x] @ [weight_flat ; loop_weight] + bias)
// M=20000, N=128, K=2176.  BM=128, BN=128, BK=16, 256 threads, 8x8/thread.
// Accumulators are f32x2 pairs along M (lane0=m, lane1=m+1); B values are
// stored DUPLICATED in shared so no per-iteration packing movs are needed.

__global__ void __launch_bounds__(256) k_gemm(
    const float* __restrict__ x, const float* __restrict__ weight,
    const float* __restrict__ loopw, const float* __restrict__ bias,
    float* __restrict__ out, int M)
{
    __shared__ float  As[16][128];        // [k][m]   8 KB
    __shared__ float2 Bs[16][130];        // [k][n] duplicated, padded  16.6 KB

    int t = threadIdx.x;
    int ty = t >> 4, tx = t & 15;
    int m0 = ty * 8, n0 = tx * 8;
    int blockM = blockIdx.x * 128;

    ull acc[4][8];
#pragma unroll
    for (int i = 0; i < 4; i++)
#pragma unroll
        for (int j = 0; j < 8; j++) acc[i][j] = 0ull;

    // A staging: thread loads row ar, k-cols [kc, kc+8)
    int ar = t >> 1;
    int kc = (t & 1) * 8;
    int arow = blockM + ar;
    // B staging: thread loads k-row br, n-cols [bc, bc+8)
    int br = t & 15;
    int bc = (t >> 4) * 8;

    // ---- prologue: load tile 0 into registers ----
    float4 av0, av1, bv0, bv1;
    {
        av0 = make_float4(0.f, 0.f, 0.f, 0.f); av1 = av0;
        if (arow < M) {
            const float* Ap = g_G + (size_t)arow * KG + kc;   // tile0 is in G region
            av0 = *(const float4*)Ap;
            av1 = *(const float4*)(Ap + 4);
        }
        const float* Bp = weight + (size_t)br * DOUT + bc;
        bv0 = *(const float4*)Bp;
        bv1 = *(const float4*)(Bp + 4);
    }

    for (int k0 = 0; k0 < KTOT; k0 += 16) {
        __syncthreads();
        // store staged tile
        As[kc + 0][ar] = av0.x; As[kc + 1][ar] = av0.y;
        As[kc + 2][ar] = av0.z; As[kc + 3][ar] = av0.w;
        As[kc + 4][ar] = av1.x; As[kc + 5][ar] = av1.y;
        As[kc + 6][ar] = av1.z; As[kc + 7][ar] = av1.w;
        *(float4*)&Bs[br][bc + 0] = make_float4(bv0.x, bv0.x, bv0.y, bv0.y);
        *(float4*)&Bs[br][bc + 2] = make_float4(bv0.z, bv0.z, bv0.w, bv0.w);
        *(float4*)&Bs[br][bc + 4] = make_float4(bv1.x, bv1.x, bv1.y, bv1.y);
        *(float4*)&Bs[br][bc + 6] = make_float4(bv1.z, bv1.z, bv1.w, bv1.w);
        __syncthreads();

        // prefetch next tile into registers (overlaps with compute below)
        int kn = k0 + 16;
        if (kn < KTOT) {
            av0 = make_float4(0.f, 0.f, 0.f, 0.f); av1 = av0;
            if (arow < M) {
                const float* Ap;
                int ka = kn + kc;
                if (ka < KG) Ap = g_G + (size_t)arow * KG + ka;
                else         Ap = x + (size_t)arow * DIN + (ka - KG);
                av0 = *(const float4*)Ap;
                av1 = *(const float4*)(Ap + 4);
            }
            int kb = kn + br;
            const float* Bp = (kb < KG) ? (weight + (size_t)kb * DOUT + bc)
                                        : (loopw + (size_t)(kb - KG) * DOUT + bc);
            bv0 = *(const float4*)Bp;
            bv1 = *(const float4*)(Bp + 4);
        }

        // compute 16 k-steps
#pragma unroll
        for (int kk = 0; kk < 16; kk++) {
            const ull* ap = (const ull*)&As[kk][m0];
            ull a0 = ap[0], a1 = ap[1], a2 = ap[2], a3 = ap[3];
            const ull* bp = (const ull*)&Bs[kk][n0];
            ull b[8];
#pragma unroll
            for (int j = 0; j < 8; j++) b[j] = bp[j];
#pragma unroll
            for (int j = 0; j < 8; j++) {
                acc[0][j] = f2fma(a0, b[j], acc[0][j]);
                acc[1][j] = f2fma(a1, b[j], acc[1][j]);
                acc[2][j] = f2fma(a2, b[j], acc[2][j]);
                acc[3][j] = f2fma(a3, b[j], acc[3][j]);
            }
        }
    }

    // epilogue: bias + relu + store
    float4 bz0 = *(const float4*)(bias + n0);
    float4 bz1 = *(const float4*)(bias + n0 + 4);
#pragma unroll
    for (int i = 0; i < 4; i++) {
        int mlo = blockM + m0 + 2 * i;
        if (mlo < M) {
            float4 o0, o1;
            o0.x = fmaxf(f2lo(acc[i][0]) + bz0.x, 0.f);
            o0.y = fmaxf(f2lo(acc[i][1]) + bz0.y, 0.f);
            o0.z = fmaxf(f2lo(acc[i][2]) + bz0.z, 0.f);
            o0.w = fmaxf(f2lo(acc[i][3]) + bz0.w, 0.f);
            o1.x = fmaxf(f2lo(acc[i][4]) + bz1.x, 0.f);
            o1.y = fmaxf(f2lo(acc[i][5]) + bz1.y, 0.f);
            o1.z = fmaxf(f2lo(acc[i][6]) + bz1.z, 0.f);
            o1.w = fmaxf(f2lo(acc[i][7]) + bz1.w, 0.f);
            *(float4*)(out + (size_t)mlo * DOUT + n0)     = o0;
            *(float4*)(out + (size_t)mlo * DOUT + n0 + 4) = o1;
        }
        int mhi = mlo + 1;
        if (mhi < M) {
            float4 o0, o1;
            o0.x = fmaxf(f2hi(acc[i][0]) + bz0.x, 0.f);
            o0.y = fmaxf(f2hi(acc[i][1]) + bz0.y, 0.f);
            o0.z = fmaxf(f2hi(acc[i][2]) + bz0.z, 0.f);
            o0.w = fmaxf(f2hi(acc[i][3]) + bz0.w, 0.f);
            o1.x = fmaxf(f2hi(acc[i][4]) + bz1.x, 0.f);
            o1.y = fmaxf(f2hi(acc[i][5]) + bz1.y, 0.f);
            o1.z = fmaxf(f2hi(acc[i][6]) + bz1.z, 0.f);
            o1.w = fmaxf(f2hi(acc[i][7]) + bz1.w, 0.f);
            *(float4*)(out + (size_t)mhi * DOUT + n0)     = o0;
            *(float4*)(out + (size_t)mhi * DOUT + n0 + 4) = o1;
        }
    }
}

// ---------------- launch ----------------

extern "C" void kernel_launch(void* const* d_in, const int* in_sizes, int n_in,
                              void* d_out, int out_size) {
    const float* x      = (const float*)d_in[0];
    const float* weight = (const float*)d_in[1];
    const float* wcomp  = (const float*)d_in[2];
    const float* bias   = (const float*)d_in[3];
    const float* loopw  = (const float*)d_in[4];
    const float* norm   = (const float*)d_in[5];
    const int*   src    = (const int*)d_in[6];
    const int*   dst    = (const int*)d_in[7];
    const int*   et     = (const int*)d_in[8];
    float* out = (float*)d_out;

    int N = in_sizes[0] / DIN;
    int E = in_sizes[6];

    k_init<<<(N + 255) / 256, 256>>>(N);
    k_hist<<<(E + 255) / 256, 256>>>(dst, E);
    k_scan<<<1, 1024>>>(N);
    k_scatter<<<(E + 255) / 256, 256>>>(dst, E);
    k_edge<<<N, 128>>>(x, wcomp, norm, src, et);
    k_gemm<<<(N + 127) / 128, 256>>>(x, weight, loopw, bias, out, N);
}

// round 3
// speedup vs baseline: 1.7980x; 1.7980x over previous
#include <cuda_runtime.h>

#define NNODES 20000
#define NEDGES 640000
#define RREL 64
#define BBASIS 16
#define DIN 128
#define DOUT 128
#define KG 2048
#define KTOT 2176
#define BM 32
#define NTILES (NNODES / BM)     /* 625 exact */
#define GEMM_GRID 296

typedef unsigned long long ull;

__device__ __forceinline__ ull f2fma(ull a, ull b, ull c) {
    ull d; asm("fma.rn.f32x2 %0, %1, %2, %3;" : "=l"(d) : "l"(a), "l"(b), "l"(c)); return d;
}
__device__ __forceinline__ ull f2dup(float v) {
    ull d; asm("mov.b64 %0, {%1, %1};" : "=l"(d) : "f"(v)); return d;
}
__device__ __forceinline__ float f2lo(ull v){ return __uint_as_float((unsigned)v); }
__device__ __forceinline__ float f2hi(ull v){ return __uint_as_float((unsigned)(v >> 32)); }

union F4U2 { float4 f4; ull u[2]; };

// ---- scratch (zero-initialized at load; counters re-zeroed by k_gemm each call) ----
__device__ float g_G[(size_t)NNODES * KG];
__device__ int g_cnt[NNODES];
__device__ int g_cur[NNODES];
__device__ int g_off[NNODES + 1];
__device__ int g_perm[NEDGES];
__device__ int g_tile;

// ---------------- counting sort by dst ----------------

__global__ void k_hist(const int* __restrict__ dst, int e) {
    int i = blockIdx.x * blockDim.x + threadIdx.x;
    if (i < e) atomicAdd(&g_cnt[dst[i]], 1);
}

__global__ void k_scan(int n) {
    __shared__ int sums[1024];
    int t = threadIdx.x;
    if (t == 0) g_tile = 0;          // reset GEMM work-steal counter for this replay
    const int chunk = (n + 1023) / 1024;
    int base = t * chunk;
    int s = 0;
    for (int j = 0; j < chunk; j++) {
        int idx = base + j;
        if (idx < n) s += g_cnt[idx];
    }
    sums[t] = s;
    __syncthreads();
    for (int d = 1; d < 1024; d <<= 1) {
        int v = (t >= d) ? sums[t - d] : 0;
        __syncthreads();
        sums[t] += v;
        __syncthreads();
    }
    int run = (t == 0) ? 0 : sums[t - 1];
    for (int j = 0; j < chunk; j++) {
        int idx = base + j;
        if (idx < n) { g_off[idx] = run; run += g_cnt[idx]; }
    }
    if (t == 1023) g_off[n] = run;
}

__global__ void k_scatter(const int* __restrict__ dst, int e) {
    int i = blockIdx.x * blockDim.x + threadIdx.x;
    if (i < e) {
        int d = dst[i];
        int p = g_off[d] + atomicAdd(&g_cur[d], 1);
        g_perm[p] = i;
    }
}

// ---------------- edge accumulation ----------------
// One block per dst node, 128 threads. Thread t owns x-column t; 16 basis
// accumulators in registers as 8 f32x2. x row read from L2 exactly once per
// edge (coalesced 512B). w_comp row: 4 conflict-free LDS.128 broadcasts.

__global__ void __launch_bounds__(128) k_edge(
    const float* __restrict__ x, const float* __restrict__ wcomp,
    const float* __restrict__ norm, const int* __restrict__ src,
    const int* __restrict__ et)
{
    __shared__ float4 wc_s[RREL * 4];
    int t = threadIdx.x;
    const float4* wcv = (const float4*)wcomp;
    wc_s[t]       = wcv[t];
    wc_s[t + 128] = wcv[t + 128];
    __syncthreads();

    int d = blockIdx.x;
    ull acc[8];
#pragma unroll
    for (int j = 0; j < 8; j++) acc[j] = 0ull;

    int k0 = g_off[d], k1 = g_off[d + 1];

    int s = 0, r = 0; float nv = 0.f;
    if (k0 < k1) {
        int e = g_perm[k0];
        s = src[e]; r = et[e]; nv = norm[e];
    }
    for (int k = k0; k < k1; k++) {
        int cs = s, cr = r; float cn = nv;
        if (k + 1 < k1) {
            int e = g_perm[k + 1];
            s = src[e]; r = et[e]; nv = norm[e];
        }
        float xv = __ldg(x + (size_t)cs * DIN + t) * cn;
        ull xd = f2dup(xv);
        const float4* wr = &wc_s[cr << 2];
        F4U2 w0, w1, w2, w3;
        w0.f4 = wr[0]; w1.f4 = wr[1]; w2.f4 = wr[2]; w3.f4 = wr[3];
        acc[0] = f2fma(w0.u[0], xd, acc[0]);
        acc[1] = f2fma(w0.u[1], xd, acc[1]);
        acc[2] = f2fma(w1.u[0], xd, acc[2]);
        acc[3] = f2fma(w1.u[1], xd, acc[3]);
        acc[4] = f2fma(w2.u[0], xd, acc[4]);
        acc[5] = f2fma(w2.u[1], xd, acc[5]);
        acc[6] = f2fma(w3.u[0], xd, acc[6]);
        acc[7] = f2fma(w3.u[1], xd, acc[7]);
    }

    float* gp = g_G + (size_t)d * KG + t;
#pragma unroll
    for (int j = 0; j < 8; j++) {
        gp[(2 * j) * DIN]     = f2lo(acc[j]);
        gp[(2 * j + 1) * DIN] = f2hi(acc[j]);
    }
}

// ---------------- fused GEMM, work-stealing, f32x2 paired along N ----------------
// out = relu([G | x] @ [weight ; loop_weight] + bias)
// Tiles: BM=32 x BN=128, BK=16, 128 threads/CTA, 296 persistent CTAs stealing
// 625 tiles. Thread tile 4m x 8n (n split 4+4 for conflict-free LDS.128).

__global__ void __launch_bounds__(128) k_gemm(
    const float* __restrict__ x, const float* __restrict__ weight,
    const float* __restrict__ loopw, const float* __restrict__ bias,
    float* __restrict__ out)
{
    __shared__ float As[2][16][36];
    __shared__ float Bs[2][16][132];
    __shared__ int s_tile;

    int t = threadIdx.x;

    // re-zero sort counters for the NEXT replay (done after all uses this call)
    int gid = blockIdx.x * 128 + t;
    if (gid < NNODES) { g_cnt[gid] = 0; g_cur[gid] = 0; }

    int tx = t & 15, ty = t >> 4;
    int m0 = ty * 4;
    int nA = tx * 4, nB = 64 + tx * 4;

    // staging maps
    int ar = t >> 2;            // 0..31
    int kc = (t & 3) << 2;      // 0,4,8,12
    int br = t >> 3;            // 0..15
    int bc = (t & 7) << 4;      // 0,16,...,112

    float4 bzA = *(const float4*)(bias + nA);
    float4 bzB = *(const float4*)(bias + nB);

    for (;;) {
        __syncthreads();
        if (t == 0) s_tile = atomicAdd(&g_tile, 1);
        __syncthreads();
        int tile = s_tile;
        if (tile >= NTILES) break;
        int blockM = tile * BM;
        int arow = blockM + ar;

        ull acc[4][4];
#pragma unroll
        for (int i = 0; i < 4; i++)
#pragma unroll
            for (int j = 0; j < 4; j++) acc[i][j] = 0ull;

        // prologue: tile 0 (always in G / weight region since KG = 128*16)
        float4 av = *(const float4*)(g_G + (size_t)arow * KG + kc);
        float4 bv0 = *(const float4*)(weight + (size_t)br * DOUT + bc);
        float4 bv1 = *(const float4*)(weight + (size_t)br * DOUT + bc + 4);
        float4 bv2 = *(const float4*)(weight + (size_t)br * DOUT + bc + 8);
        float4 bv3 = *(const float4*)(weight + (size_t)br * DOUT + bc + 12);

#pragma unroll 1
        for (int kt = 0; kt < 136; kt++) {
            int buf = kt & 1;
            As[buf][kc + 0][ar] = av.x;
            As[buf][kc + 1][ar] = av.y;
            As[buf][kc + 2][ar] = av.z;
            As[buf][kc + 3][ar] = av.w;
            *(float4*)&Bs[buf][br][bc + 0]  = bv0;
            *(float4*)&Bs[buf][br][bc + 4]  = bv1;
            *(float4*)&Bs[buf][br][bc + 8]  = bv2;
            *(float4*)&Bs[buf][br][bc + 12] = bv3;
            __syncthreads();

            // prefetch next tile
            if (kt + 1 < 136) {
                int ka = (kt + 1) * 16 + kc;
                const float* Ap = (ka < KG) ? (g_G + (size_t)arow * KG + ka)
                                            : (x + (size_t)arow * DIN + (ka - KG));
                av = *(const float4*)Ap;
                int kb = (kt + 1) * 16 + br;
                const float* Bp = (kb < KG) ? (weight + (size_t)kb * DOUT + bc)
                                            : (loopw + (size_t)(kb - KG) * DOUT + bc);
                bv0 = *(const float4*)(Bp + 0);
                bv1 = *(const float4*)(Bp + 4);
                bv2 = *(const float4*)(Bp + 8);
                bv3 = *(const float4*)(Bp + 12);
            }

#pragma unroll
            for (int kk = 0; kk < 16; kk++) {
                F4U2 a; a.f4 = *(const float4*)&As[buf][kk][m0];
                ull ad0 = f2dup(a.f4.x), ad1 = f2dup(a.f4.y);
                ull ad2 = f2dup(a.f4.z), ad3 = f2dup(a.f4.w);
                F4U2 bA, bB;
                bA.f4 = *(const float4*)&Bs[buf][kk][nA];
                bB.f4 = *(const float4*)&Bs[buf][kk][nB];
                acc[0][0] = f2fma(ad0, bA.u[0], acc[0][0]);
                acc[0][1] = f2fma(ad0, bA.u[1], acc[0][1]);
                acc[0][2] = f2fma(ad0, bB.u[0], acc[0][2]);
                acc[0][3] = f2fma(ad0, bB.u[1], acc[0][3]);
                acc[1][0] = f2fma(ad1, bA.u[0], acc[1][0]);
                acc[1][1] = f2fma(ad1, bA.u[1], acc[1][1]);
                acc[1][2] = f2fma(ad1, bB.u[0], acc[1][2]);
                acc[1][3] = f2fma(ad1, bB.u[1], acc[1][3]);
                acc[2][0] = f2fma(ad2, bA.u[0], acc[2][0]);
                acc[2][1] = f2fma(ad2, bA.u[1], acc[2][1]);
                acc[2][2] = f2fma(ad2, bB.u[0], acc[2][2]);
                acc[2][3] = f2fma(ad2, bB.u[1], acc[2][3]);
                acc[3][0] = f2fma(ad3, bA.u[0], acc[3][0]);
                acc[3][1] = f2fma(ad3, bA.u[1], acc[3][1]);
                acc[3][2] = f2fma(ad3, bB.u[0], acc[3][2]);
                acc[3][3] = f2fma(ad3, bB.u[1], acc[3][3]);
            }
            __syncthreads();
        }

        // epilogue
#pragma unroll
        for (int i = 0; i < 4; i++) {
            int m = blockM + m0 + i;
            float4 oA, oB;
            oA.x = fmaxf(f2lo(acc[i][0]) + bzA.x, 0.f);
            oA.y = fmaxf(f2hi(acc[i][0]) + bzA.y, 0.f);
            oA.z = fmaxf(f2lo(acc[i][1]) + bzA.z, 0.f);
            oA.w = fmaxf(f2hi(acc[i][1]) + bzA.w, 0.f);
            oB.x = fmaxf(f2lo(acc[i][2]) + bzB.x, 0.f);
            oB.y = fmaxf(f2hi(acc[i][2]) + bzB.y, 0.f);
            oB.z = fmaxf(f2lo(acc[i][3]) + bzB.z, 0.f);
            oB.w = fmaxf(f2hi(acc[i][3]) + bzB.w, 0.f);
            *(float4*)(out + (size_t)m * DOUT + nA) = oA;
            *(float4*)(out + (size_t)m * DOUT + nB) = oB;
        }
    }
}

// ---------------- launch ----------------

extern "C" void kernel_launch(void* const* d_in, const int* in_sizes, int n_in,
                              void* d_out, int out_size) {
    const float* x      = (const float*)d_in[0];
    const float* weight = (const float*)d_in[1];
    const float* wcomp  = (const float*)d_in[2];
    const float* bias   = (const float*)d_in[3];
    const float* loopw  = (const float*)d_in[4];
    const float* norm   = (const float*)d_in[5];
    const int*   src    = (const int*)d_in[6];
    const int*   dst    = (const int*)d_in[7];
    const int*   et     = (const int*)d_in[8];
    float* out = (float*)d_out;

    int N = in_sizes[0] / DIN;
    int E = in_sizes[6];

    k_hist<<<(E + 255) / 256, 256>>>(dst, E);
    k_scan<<<1, 1024>>>(N);
    k_scatter<<<(E + 255) / 256, 256>>>(dst, E);
    k_edge<<<N, 128>>>(x, wcomp, norm, src, et);
    k_gemm<<<GEMM_GRID, 128>>>(x, weight, loopw, bias, out);
}

// round 5
// speedup vs baseline: 4.0156x; 2.2334x over previous
#include <cuda_runtime.h>
#include <cuda_bf16.h>
#include <cstdint>

#define NNODES 20000
#define NEDGES 640000
#define RREL 64
#define BBASIS 16
#define DIN 128
#define KG 2048
#define KTOT 2176
#define AROWS 20096          /* padded; pad rows stay zero forever */
#define NTILES 313           /* ceil(20000/64) */
#define GEMM_GRID 296
#define EDGE_GRID 1184
#define KSTAGES 68           /* 2176 / 32 */

/* smem stage layout (bytes), 80B row stride for conflict-free ldmatrix */
#define SA_HI 0
#define SA_LO 5120
#define SB_HI 10240
#define SB_LO 20480
#define STAGE_BYTES 30720
#define SMEM_TOTAL (2 * STAGE_BYTES)

typedef unsigned long long ull;

// ---------------- helpers ----------------

__device__ __forceinline__ ull f2fma(ull a, ull b, ull c) {
    ull d; asm("fma.rn.f32x2 %0, %1, %2, %3;" : "=l"(d) : "l"(a), "l"(b), "l"(c)); return d;
}
__device__ __forceinline__ ull f2dup(float v) {
    ull d; asm("mov.b64 %0, {%1, %1};" : "=l"(d) : "f"(v)); return d;
}
__device__ __forceinline__ float f2lo(ull v){ return __uint_as_float((unsigned)v); }
__device__ __forceinline__ float f2hi(ull v){ return __uint_as_float((unsigned)(v >> 32)); }

union F4U2 { float4 f4; ull u[2]; };

__device__ __forceinline__ uint32_t smem_u32(const void* p) {
    uint32_t a;
    asm("{ .reg .u64 t; cvta.to.shared.u64 t, %1; cvt.u32.u64 %0, t; }" : "=r"(a) : "l"(p));
    return a;
}
__device__ __forceinline__ void cvt_split(float v, __nv_bfloat16* hi, __nv_bfloat16* lo) {
    __nv_bfloat16 h = __float2bfloat16(v);
    *hi = h;
    *lo = __float2bfloat16(v - __bfloat162float(h));
}

__device__ __forceinline__ void cp16(uint32_t dst, const void* src) {
    asm volatile("cp.async.cg.shared.global [%0], [%1], 16;" :: "r"(dst), "l"(src) : "memory");
}
__device__ __forceinline__ void cp_commit() {
    asm volatile("cp.async.commit_group;" ::: "memory");
}
template <int N>
__device__ __forceinline__ void cp_wait() {
    asm volatile("cp.async.wait_group %0;" :: "n"(N) : "memory");
}

__device__ __forceinline__ void ldx4(uint32_t* r, uint32_t addr) {
    asm volatile("ldmatrix.sync.aligned.m8n8.x4.shared.b16 {%0,%1,%2,%3}, [%4];"
        : "=r"(r[0]), "=r"(r[1]), "=r"(r[2]), "=r"(r[3]) : "r"(addr));
}

__device__ __forceinline__ void mma_bf16(float* d, const uint32_t* a, const uint32_t* b) {
    asm volatile(
        "mma.sync.aligned.m16n8k16.row.col.f32.bf16.bf16.f32 "
        "{%0,%1,%2,%3}, {%4,%5,%6,%7}, {%8,%9}, {%0,%1,%2,%3};"
        : "+f"(d[0]), "+f"(d[1]), "+f"(d[2]), "+f"(d[3])
        : "r"(a[0]), "r"(a[1]), "r"(a[2]), "r"(a[3]), "r"(b[0]), "r"(b[1]));
}

// ---------------- scratch ----------------
__device__ __nv_bfloat16 g_Ahi[(size_t)AROWS * KTOT];
__device__ __nv_bfloat16 g_Alo[(size_t)AROWS * KTOT];
__device__ __nv_bfloat16 g_Whi[(size_t)DIN * KTOT];   // [n][k]
__device__ __nv_bfloat16 g_Wlo[(size_t)DIN * KTOT];
__device__ int g_cnt[NNODES];
__device__ int g_cur[NNODES];
__device__ int g_off[NNODES + 1];
__device__ int g_perm[NEDGES];
__device__ int g_tile;
__device__ int g_done;

// ---------------- hist + weight conversion + last-block scan ----------------

__global__ void k_histscan(const int* __restrict__ dst, int e,
                           const float* __restrict__ weight,
                           const float* __restrict__ loopw) {
    int i = blockIdx.x * blockDim.x + threadIdx.x;
    if (i < e) atomicAdd(&g_cnt[dst[i]], 1);
    if (i < DIN * KTOT) {
        int n = i & 127;
        int k = i >> 7;
        float w = (k < KG) ? weight[(size_t)k * 128 + n]
                           : loopw[(size_t)(k - KG) * 128 + n];
        __nv_bfloat16 hi, lo;
        cvt_split(w, &hi, &lo);
        g_Whi[(size_t)n * KTOT + k] = hi;
        g_Wlo[(size_t)n * KTOT + k] = lo;
    }
    __threadfence();
    __shared__ int s_last;
    if (threadIdx.x == 0) s_last = atomicAdd(&g_done, 1);
    __syncthreads();
    if (s_last == (int)gridDim.x - 1) {
        // last block: exclusive scan of g_cnt into g_off
        __shared__ int part[256];
        int t = threadIdx.x;
        const int chunk = 79;                 // 256*79 >= 20000
        int base = t * chunk;
        int s = 0;
        for (int j = 0; j < chunk; j++) {
            int idx = base + j;
            if (idx < NNODES) s += g_cnt[idx];
        }
        part[t] = s;
        __syncthreads();
        for (int d = 1; d < 256; d <<= 1) {
            int v = (t >= d) ? part[t - d] : 0;
            __syncthreads();
            part[t] += v;
            __syncthreads();
        }
        int run = (t == 0) ? 0 : part[t - 1];
        for (int j = 0; j < chunk; j++) {
            int idx = base + j;
            if (idx < NNODES) { g_off[idx] = run; run += g_cnt[idx]; }
        }
        if (t == 255) g_off[NNODES] = run;
        if (t == 0) { g_done = 0; g_tile = 0; }
    }
}

__global__ void k_scatter(const int* __restrict__ dst, int e) {
    int i = blockIdx.x * blockDim.x + threadIdx.x;
    if (i < e) {
        int d = dst[i];
        int p = g_off[d] + atomicAdd(&g_cur[d], 1);
        g_perm[p] = i;
    }
}

// ---------------- edge accumulation (persistent) ----------------

__global__ void __launch_bounds__(128) k_edge(
    const float* __restrict__ x, const float* __restrict__ wcomp,
    const float* __restrict__ norm, const int* __restrict__ src,
    const int* __restrict__ et)
{
    __shared__ float4 wc_s[RREL * 4];
    int t = threadIdx.x;
    const float4* wcv = (const float4*)wcomp;
    wc_s[t]       = wcv[t];
    wc_s[t + 128] = wcv[t + 128];
    __syncthreads();

    for (int d = blockIdx.x; d < NNODES; d += gridDim.x) {
        ull acc[8];
#pragma unroll
        for (int j = 0; j < 8; j++) acc[j] = 0ull;

        int k0 = g_off[d], k1 = g_off[d + 1];
        int k = k0;
        for (; k + 2 <= k1; k += 2) {
            int e0 = g_perm[k], e1 = g_perm[k + 1];
            int s0 = src[e0], s1 = src[e1];
            int r0 = et[e0],  r1 = et[e1];
            float n0 = norm[e0], n1 = norm[e1];
            float xv0 = __ldg(x + (size_t)s0 * DIN + t) * n0;
            float xv1 = __ldg(x + (size_t)s1 * DIN + t) * n1;
            ull xd0 = f2dup(xv0), xd1 = f2dup(xv1);
            const float4* wr0 = &wc_s[r0 << 2];
            const float4* wr1 = &wc_s[r1 << 2];
            F4U2 w;
#pragma unroll
            for (int j = 0; j < 4; j++) {
                w.f4 = wr0[j];
                acc[2 * j]     = f2fma(w.u[0], xd0, acc[2 * j]);
                acc[2 * j + 1] = f2fma(w.u[1], xd0, acc[2 * j + 1]);
            }
#pragma unroll
            for (int j = 0; j < 4; j++) {
                w.f4 = wr1[j];
                acc[2 * j]     = f2fma(w.u[0], xd1, acc[2 * j]);
                acc[2 * j + 1] = f2fma(w.u[1], xd1, acc[2 * j + 1]);
            }
        }
        if (k < k1) {
            int e0 = g_perm[k];
            int s0 = src[e0], r0 = et[e0];
            float xv0 = __ldg(x + (size_t)s0 * DIN + t) * norm[e0];
            ull xd0 = f2dup(xv0);
            const float4* wr0 = &wc_s[r0 << 2];
            F4U2 w;
#pragma unroll
            for (int j = 0; j < 4; j++) {
                w.f4 = wr0[j];
                acc[2 * j]     = f2fma(w.u[0], xd0, acc[2 * j]);
                acc[2 * j + 1] = f2fma(w.u[1], xd0, acc[2 * j + 1]);
            }
        }

        size_t base = (size_t)d * KTOT;
        __nv_bfloat16 hi, lo;
#pragma unroll
        for (int j = 0; j < 8; j++) {
            cvt_split(f2lo(acc[j]), &hi, &lo);
            g_Ahi[base + (2 * j) * DIN + t] = hi;
            g_Alo[base + (2 * j) * DIN + t] = lo;
            cvt_split(f2hi(acc[j]), &hi, &lo);
            g_Ahi[base + (2 * j + 1) * DIN + t] = hi;
            g_Alo[base + (2 * j + 1) * DIN + t] = lo;
        }
        cvt_split(__ldg(x + (size_t)d * DIN + t), &hi, &lo);
        g_Ahi[base + KG + t] = hi;
        g_Alo[base + KG + t] = lo;
    }
}

// ---------------- mma.sync GEMM ----------------
// out = relu([Ahi+Alo] @ [Whi+Wlo]^T + bias) via 3 bf16 products, fp32 accum.
// BM=64, BN=128, BK=32; 8 warps as 2m x 4n (warp tile 32x32).
// smem rows are 80B-strided: ldmatrix 8-row groups hit distinct banks.

extern __shared__ char dynsmem[];

__global__ void __launch_bounds__(256, 2) k_gemm_mma(const float* __restrict__ bias,
                                                     float* __restrict__ out)
{
    __shared__ int s_tile;
    int t = threadIdx.x;
    int l = t & 31, wid = t >> 5;

    // re-zero sort counters for next graph replay
    int gid = blockIdx.x * 256 + t;
    if (gid < NNODES) { g_cnt[gid] = 0; g_cur[gid] = 0; }

    uint32_t su = smem_u32(dynsmem);

    int wm = (wid & 1) * 32;         // warp m offset in tile
    int wn = (wid >> 1) * 32;        // warp n offset

    // ldmatrix lane offsets (bytes within stage)
    uint32_t aoff[2], boff[2];
#pragma unroll
    for (int mf = 0; mf < 2; mf++)
        aoff[mf] = (uint32_t)((wm + mf * 16 + (l & 15)) * 80 + (l >> 4) * 16);
#pragma unroll
    for (int nb = 0; nb < 2; nb++)
        boff[nb] = (uint32_t)(SB_HI + (wn + nb * 16 + ((l >> 4) << 3) + (l & 7)) * 80
                              + ((l >> 3) & 1) * 16);

    // cp.async staging maps
    int arow = t >> 2;               // 0..63   (A row within tile)
    int seg  = t & 3;                // 16B segment within 64B row
    int brow0 = t >> 2;              // B rows handled: brow0 and brow0+64
    const __nv_bfloat16* pBh0 = g_Whi + (size_t)brow0 * KTOT + seg * 8;
    const __nv_bfloat16* pBh1 = g_Whi + (size_t)(brow0 + 64) * KTOT + seg * 8;
    const __nv_bfloat16* pBl0 = g_Wlo + (size_t)brow0 * KTOT + seg * 8;
    const __nv_bfloat16* pBl1 = g_Wlo + (size_t)(brow0 + 64) * KTOT + seg * 8;
    uint32_t dA  = (uint32_t)(arow * 80 + seg * 16);
    uint32_t dB0 = (uint32_t)(SB_HI + brow0 * 80 + seg * 16);
    uint32_t dB1 = (uint32_t)(SB_HI + (brow0 + 64) * 80 + seg * 16);

    for (;;) {
        __syncthreads();
        if (t == 0) s_tile = atomicAdd(&g_tile, 1);
        __syncthreads();
        int tile = s_tile;
        if (tile >= NTILES) break;
        int tileM = tile * 64;

        const __nv_bfloat16* pAh = g_Ahi + (size_t)(tileM + arow) * KTOT + seg * 8;
        const __nv_bfloat16* pAl = g_Alo + (size_t)(tileM + arow) * KTOT + seg * 8;

        float acc[2][4][4];
#pragma unroll
        for (int mf = 0; mf < 2; mf++)
#pragma unroll
            for (int nf = 0; nf < 4; nf++)
#pragma unroll
                for (int q = 0; q < 4; q++) acc[mf][nf][q] = 0.f;

#pragma unroll 1
        for (int it = 0; it < KSTAGES; it++) {
            int buf = it & 1;
            if (it == 0) {
                uint32_t sb = su;                      // stage 0
                cp16(sb + dA,          pAh);
                cp16(sb + SA_LO + dA,  pAl);
                cp16(sb + dB0,         pBh0);
                cp16(sb + dB1,         pBh1);
                cp16(sb + SB_LO - SB_HI + dB0, pBl0);
                cp16(sb + SB_LO - SB_HI + dB1, pBl1);
                cp_commit();
            }
            if (it + 1 < KSTAGES) {
                uint32_t sb = su + (buf ^ 1) * STAGE_BYTES;
                int koff = (it + 1) * 32;
                cp16(sb + dA,          pAh + koff);
                cp16(sb + SA_LO + dA,  pAl + koff);
                cp16(sb + dB0,         pBh0 + koff);
                cp16(sb + dB1,         pBh1 + koff);
                cp16(sb + SB_LO - SB_HI + dB0, pBl0 + koff);
                cp16(sb + SB_LO - SB_HI + dB1, pBl1 + koff);
                cp_commit();
                cp_wait<1>();
            } else {
                cp_wait<0>();
            }
            __syncthreads();

            uint32_t sb = su + buf * STAGE_BYTES;
#pragma unroll
            for (int ks = 0; ks < 2; ks++) {
                uint32_t ah[2][4], al[2][4], bh[4][2], bl[4][2];
                ldx4(ah[0], sb + aoff[0] + ks * 32);
                ldx4(ah[1], sb + aoff[1] + ks * 32);
                ldx4(al[0], sb + SA_LO + aoff[0] + ks * 32);
                ldx4(al[1], sb + SA_LO + aoff[1] + ks * 32);
                {
                    uint32_t r[4];
                    ldx4(r, sb + boff[0] + ks * 32);
                    bh[0][0] = r[0]; bh[0][1] = r[1]; bh[1][0] = r[2]; bh[1][1] = r[3];
                    ldx4(r, sb + boff[1] + ks * 32);
                    bh[2][0] = r[0]; bh[2][1] = r[1]; bh[3][0] = r[2]; bh[3][1] = r[3];
                    ldx4(r, sb + (SB_LO - SB_HI) + boff[0] + ks * 32);
                    bl[0][0] = r[0]; bl[0][1] = r[1]; bl[1][0] = r[2]; bl[1][1] = r[3];
                    ldx4(r, sb + (SB_LO - SB_HI) + boff[1] + ks * 32);
                    bl[2][0] = r[0]; bl[2][1] = r[1]; bl[3][0] = r[2]; bl[3][1] = r[3];
                }
#pragma unroll
                for (int mf = 0; mf < 2; mf++)
#pragma unroll
                    for (int nf = 0; nf < 4; nf++) {
                        mma_bf16(acc[mf][nf], ah[mf], bh[nf]);
                        mma_bf16(acc[mf][nf], ah[mf], bl[nf]);
                        mma_bf16(acc[mf][nf], al[mf], bh[nf]);
                    }
            }
            __syncthreads();
        }

        // epilogue: bias + relu + store
#pragma unroll
        for (int mf = 0; mf < 2; mf++) {
#pragma unroll
            for (int nf = 0; nf < 4; nf++) {
                int col = wn + nf * 8 + 2 * (l & 3);
                float b0 = bias[col], b1 = bias[col + 1];
                int r0 = tileM + wm + mf * 16 + (l >> 2);
                int r1 = r0 + 8;
                if (r0 < NNODES) {
                    float2 o;
                    o.x = fmaxf(acc[mf][nf][0] + b0, 0.f);
                    o.y = fmaxf(acc[mf][nf][1] + b1, 0.f);
                    *(float2*)(out + (size_t)r0 * DIN + col) = o;
                }
                if (r1 < NNODES) {
                    float2 o;
                    o.x = fmaxf(acc[mf][nf][2] + b0, 0.f);
                    o.y = fmaxf(acc[mf][nf][3] + b1, 0.f);
                    *(float2*)(out + (size_t)r1 * DIN + col) = o;
                }
            }
        }
    }
}

// ---------------- launch ----------------

extern "C" void kernel_launch(void* const* d_in, const int* in_sizes, int n_in,
                              void* d_out, int out_size) {
    const float* x      = (const float*)d_in[0];
    const float* weight = (const float*)d_in[1];
    const float* wcomp  = (const float*)d_in[2];
    const float* bias   = (const float*)d_in[3];
    const float* loopw  = (const float*)d_in[4];
    const float* norm   = (const float*)d_in[5];
    const int*   src    = (const int*)d_in[6];
    const int*   dst    = (const int*)d_in[7];
    const int*   et     = (const int*)d_in[8];
    float* out = (float*)d_out;

    int E = in_sizes[6];

    cudaFuncSetAttribute(k_gemm_mma, cudaFuncAttributeMaxDynamicSharedMemorySize,
                         SMEM_TOTAL);

    k_histscan<<<(E + 255) / 256, 256>>>(dst, E, weight, loopw);
    k_scatter<<<(E + 255) / 256, 256>>>(dst, E);
    k_edge<<<EDGE_GRID, 128>>>(x, wcomp, norm, src, et);
    k_gemm_mma<<<GEMM_GRID, 256, SMEM_TOTAL>>>(bias, out);
}

// round 6
// speedup vs baseline: 4.3160x; 1.0748x over previous
#include <cuda_runtime.h>
#include <cuda_bf16.h>
#include <cstdint>

#define NNODES 20000
#define NEDGES 640000
#define RREL 64
#define BBASIS 16
#define DIN 128
#define KG 2048
#define KTOT 2176
#define AROWS 20096          /* padded; pad rows stay zero forever */
#define NTILES 313           /* ceil(20000/64) */
#define GEMM_GRID 296
#define EDGE_GRID 1184
#define KSTAGES 68           /* 2176 / 32 */

/* smem stage layout (bytes), 80B row stride for conflict-free ldmatrix */
#define SA_HI 0
#define SA_LO 5120
#define SB_HI 10240
#define SB_LO 20480
#define STAGE_BYTES 30720
#define SMEM_TOTAL (3 * STAGE_BYTES)

typedef unsigned long long ull;

// ---------------- helpers ----------------

__device__ __forceinline__ ull f2fma(ull a, ull b, ull c) {
    ull d; asm("fma.rn.f32x2 %0, %1, %2, %3;" : "=l"(d) : "l"(a), "l"(b), "l"(c)); return d;
}
__device__ __forceinline__ ull f2dup(float v) {
    ull d; asm("mov.b64 %0, {%1, %1};" : "=l"(d) : "f"(v)); return d;
}
__device__ __forceinline__ float f2lo(ull v){ return __uint_as_float((unsigned)v); }
__device__ __forceinline__ float f2hi(ull v){ return __uint_as_float((unsigned)(v >> 32)); }

union F4U2 { float4 f4; ull u[2]; };

__device__ __forceinline__ uint32_t smem_u32(const void* p) {
    uint32_t a;
    asm("{ .reg .u64 t; cvta.to.shared.u64 t, %1; cvt.u32.u64 %0, t; }" : "=r"(a) : "l"(p));
    return a;
}
__device__ __forceinline__ void cvt_split(float v, __nv_bfloat16* hi, __nv_bfloat16* lo) {
    __nv_bfloat16 h = __float2bfloat16(v);
    *hi = h;
    *lo = __float2bfloat16(v - __bfloat162float(h));
}

__device__ __forceinline__ void cp16(uint32_t dst, const void* src) {
    asm volatile("cp.async.cg.shared.global [%0], [%1], 16;" :: "r"(dst), "l"(src) : "memory");
}
__device__ __forceinline__ void cp_commit() {
    asm volatile("cp.async.commit_group;" ::: "memory");
}
template <int N>
__device__ __forceinline__ void cp_wait() {
    asm volatile("cp.async.wait_group %0;" :: "n"(N) : "memory");
}

__device__ __forceinline__ void ldx4(uint32_t* r, uint32_t addr) {
    asm volatile("ldmatrix.sync.aligned.m8n8.x4.shared.b16 {%0,%1,%2,%3}, [%4];"
        : "=r"(r[0]), "=r"(r[1]), "=r"(r[2]), "=r"(r[3]) : "r"(addr));
}

__device__ __forceinline__ void mma_bf16(float* d, const uint32_t* a, const uint32_t* b) {
    asm volatile(
        "mma.sync.aligned.m16n8k16.row.col.f32.bf16.bf16.f32 "
        "{%0,%1,%2,%3}, {%4,%5,%6,%7}, {%8,%9}, {%0,%1,%2,%3};"
        : "+f"(d[0]), "+f"(d[1]), "+f"(d[2]), "+f"(d[3])
        : "r"(a[0]), "r"(a[1]), "r"(a[2]), "r"(a[3]), "r"(b[0]), "r"(b[1]));
}

// ---------------- scratch ----------------
__device__ __nv_bfloat16 g_Ahi[(size_t)AROWS * KTOT];
__device__ __nv_bfloat16 g_Alo[(size_t)AROWS * KTOT];
__device__ __nv_bfloat16 g_Whi[(size_t)DIN * KTOT];   // [n][k]
__device__ __nv_bfloat16 g_Wlo[(size_t)DIN * KTOT];
__device__ int g_cnt[NNODES];
__device__ int g_cur[NNODES];
__device__ int g_off[NNODES + 1];
__device__ uint2 g_edata[NEDGES];    // sorted packed: {src | et<<16, norm bits}
__device__ int g_tile;
__device__ int g_done;

// ---------------- hist + weight conversion + last-block scan ----------------

__global__ void k_histscan(const int* __restrict__ dst, int e,
                           const float* __restrict__ weight,
                           const float* __restrict__ loopw) {
    int i = blockIdx.x * blockDim.x + threadIdx.x;
    if (i < e) atomicAdd(&g_cnt[dst[i]], 1);
    if (i < DIN * KTOT) {
        int n = i & 127;
        int k = i >> 7;
        float w = (k < KG) ? weight[(size_t)k * 128 + n]
                           : loopw[(size_t)(k - KG) * 128 + n];
        __nv_bfloat16 hi, lo;
        cvt_split(w, &hi, &lo);
        g_Whi[(size_t)n * KTOT + k] = hi;
        g_Wlo[(size_t)n * KTOT + k] = lo;
    }
    __threadfence();
    __shared__ int s_last;
    if (threadIdx.x == 0) s_last = atomicAdd(&g_done, 1);
    __syncthreads();
    if (s_last == (int)gridDim.x - 1) {
        __shared__ int part[256];
        int t = threadIdx.x;
        const int chunk = 79;
        int base = t * chunk;
        int s = 0;
        for (int j = 0; j < chunk; j++) {
            int idx = base + j;
            if (idx < NNODES) s += g_cnt[idx];
        }
        part[t] = s;
        __syncthreads();
        for (int d = 1; d < 256; d <<= 1) {
            int v = (t >= d) ? part[t - d] : 0;
            __syncthreads();
            part[t] += v;
            __syncthreads();
        }
        int run = (t == 0) ? 0 : part[t - 1];
        for (int j = 0; j < chunk; j++) {
            int idx = base + j;
            if (idx < NNODES) { g_off[idx] = run; run += g_cnt[idx]; }
        }
        if (t == 255) g_off[NNODES] = run;
        if (t == 0) { g_done = 0; g_tile = 0; }
    }
}

__global__ void k_scatter(const int* __restrict__ dst, const int* __restrict__ src,
                          const int* __restrict__ et, const float* __restrict__ norm,
                          int e) {
    int i = blockIdx.x * blockDim.x + threadIdx.x;
    if (i < e) {
        int d = dst[i];
        int p = g_off[d] + atomicAdd(&g_cur[d], 1);
        g_edata[p] = make_uint2((uint32_t)src[i] | ((uint32_t)et[i] << 16),
                                __float_as_uint(norm[i]));
    }
}

// ---------------- edge accumulation (persistent, sequential edge stream) ----------------
// Thread t owns x-column t; 16 basis accumulators as 8 f32x2. Per edge: one
// sequential 8B record read, one coalesced x-row LDG, 4 LDS.128 broadcasts,
// 8 FFMA2. Unrolled x4 with hoisted LDGs for MLP.

__global__ void __launch_bounds__(128) k_edge(
    const float* __restrict__ x, const float* __restrict__ wcomp)
{
    __shared__ float4 wc_s[RREL * 4];
    int t = threadIdx.x;
    const float4* wcv = (const float4*)wcomp;
    wc_s[t]       = wcv[t];
    wc_s[t + 128] = wcv[t + 128];
    __syncthreads();

    for (int d = blockIdx.x; d < NNODES; d += gridDim.x) {
        ull acc[8];
#pragma unroll
        for (int j = 0; j < 8; j++) acc[j] = 0ull;

        int k0 = g_off[d], k1 = g_off[d + 1];
        int k = k0;
        for (; k + 4 <= k1; k += 4) {
            uint2 e0 = g_edata[k], e1 = g_edata[k + 1];
            uint2 e2 = g_edata[k + 2], e3 = g_edata[k + 3];
            int s0 = e0.x & 0xFFFF, s1 = e1.x & 0xFFFF;
            int s2 = e2.x & 0xFFFF, s3 = e3.x & 0xFFFF;
            // hoist all 4 gathers -> MLP 4
            float xv0 = __ldg(x + (size_t)s0 * DIN + t);
            float xv1 = __ldg(x + (size_t)s1 * DIN + t);
            float xv2 = __ldg(x + (size_t)s2 * DIN + t);
            float xv3 = __ldg(x + (size_t)s3 * DIN + t);
            xv0 *= __uint_as_float(e0.y);
            xv1 *= __uint_as_float(e1.y);
            xv2 *= __uint_as_float(e2.y);
            xv3 *= __uint_as_float(e3.y);
            ull xd0 = f2dup(xv0), xd1 = f2dup(xv1);
            ull xd2 = f2dup(xv2), xd3 = f2dup(xv3);
            const float4* wr0 = &wc_s[(e0.x >> 16) << 2];
            const float4* wr1 = &wc_s[(e1.x >> 16) << 2];
            const float4* wr2 = &wc_s[(e2.x >> 16) << 2];
            const float4* wr3 = &wc_s[(e3.x >> 16) << 2];
            F4U2 w;
#pragma unroll
            for (int j = 0; j < 4; j++) {
                w.f4 = wr0[j];
                acc[2 * j]     = f2fma(w.u[0], xd0, acc[2 * j]);
                acc[2 * j + 1] = f2fma(w.u[1], xd0, acc[2 * j + 1]);
            }
#pragma unroll
            for (int j = 0; j < 4; j++) {
                w.f4 = wr1[j];
                acc[2 * j]     = f2fma(w.u[0], xd1, acc[2 * j]);
                acc[2 * j + 1] = f2fma(w.u[1], xd1, acc[2 * j + 1]);
            }
#pragma unroll
            for (int j = 0; j < 4; j++) {
                w.f4 = wr2[j];
                acc[2 * j]     = f2fma(w.u[0], xd2, acc[2 * j]);
                acc[2 * j + 1] = f2fma(w.u[1], xd2, acc[2 * j + 1]);
            }
#pragma unroll
            for (int j = 0; j < 4; j++) {
                w.f4 = wr3[j];
                acc[2 * j]     = f2fma(w.u[0], xd3, acc[2 * j]);
                acc[2 * j + 1] = f2fma(w.u[1], xd3, acc[2 * j + 1]);
            }
        }
        for (; k < k1; k++) {
            uint2 e0 = g_edata[k];
            int s0 = e0.x & 0xFFFF;
            float xv0 = __ldg(x + (size_t)s0 * DIN + t) * __uint_as_float(e0.y);
            ull xd0 = f2dup(xv0);
            const float4* wr0 = &wc_s[(e0.x >> 16) << 2];
            F4U2 w;
#pragma unroll
            for (int j = 0; j < 4; j++) {
                w.f4 = wr0[j];
                acc[2 * j]     = f2fma(w.u[0], xd0, acc[2 * j]);
                acc[2 * j + 1] = f2fma(w.u[1], xd0, acc[2 * j + 1]);
            }
        }

        size_t base = (size_t)d * KTOT;
        __nv_bfloat16 hi, lo;
#pragma unroll
        for (int j = 0; j < 8; j++) {
            cvt_split(f2lo(acc[j]), &hi, &lo);
            g_Ahi[base + (2 * j) * DIN + t] = hi;
            g_Alo[base + (2 * j) * DIN + t] = lo;
            cvt_split(f2hi(acc[j]), &hi, &lo);
            g_Ahi[base + (2 * j + 1) * DIN + t] = hi;
            g_Alo[base + (2 * j + 1) * DIN + t] = lo;
        }
        cvt_split(__ldg(x + (size_t)d * DIN + t), &hi, &lo);
        g_Ahi[base + KG + t] = hi;
        g_Alo[base + KG + t] = lo;
    }
}

// ---------------- mma.sync GEMM, 3-stage pipeline, 1 sync/stage ----------------
// out = relu([Ahi+Alo] @ [Whi+Wlo]^T + bias) via 3 bf16 products, fp32 accum.
// BM=64, BN=128, BK=32; 8 warps as 2m x 4n. Products issued product-major so
// same-accumulator MMAs are 8 apart (no RAW chains).

extern __shared__ char dynsmem[];

__global__ void __launch_bounds__(256, 2) k_gemm_mma(const float* __restrict__ bias,
                                                     float* __restrict__ out)
{
    __shared__ int s_tile;
    int t = threadIdx.x;
    int l = t & 31, wid = t >> 5;

    // re-zero sort counters for next graph replay
    int gid = blockIdx.x * 256 + t;
    if (gid < NNODES) { g_cnt[gid] = 0; g_cur[gid] = 0; }

    uint32_t su = smem_u32(dynsmem);

    int wm = (wid & 1) * 32;
    int wn = (wid >> 1) * 32;

    uint32_t aoff[2], boff[2];
#pragma unroll
    for (int mf = 0; mf < 2; mf++)
        aoff[mf] = (uint32_t)((wm + mf * 16 + (l & 15)) * 80 + (l >> 4) * 16);
#pragma unroll
    for (int nb = 0; nb < 2; nb++)
        boff[nb] = (uint32_t)(SB_HI + (wn + nb * 16 + ((l >> 4) << 3) + (l & 7)) * 80
                              + ((l >> 3) & 1) * 16);

    int arow = t >> 2;
    int seg  = t & 3;
    int brow0 = t >> 2;
    const __nv_bfloat16* pBh0 = g_Whi + (size_t)brow0 * KTOT + seg * 8;
    const __nv_bfloat16* pBh1 = g_Whi + (size_t)(brow0 + 64) * KTOT + seg * 8;
    const __nv_bfloat16* pBl0 = g_Wlo + (size_t)brow0 * KTOT + seg * 8;
    const __nv_bfloat16* pBl1 = g_Wlo + (size_t)(brow0 + 64) * KTOT + seg * 8;
    uint32_t dA  = (uint32_t)(arow * 80 + seg * 16);
    uint32_t dB0 = (uint32_t)(SB_HI + brow0 * 80 + seg * 16);
    uint32_t dB1 = (uint32_t)(SB_HI + (brow0 + 64) * 80 + seg * 16);

    for (;;) {
        __syncthreads();
        if (t == 0) s_tile = atomicAdd(&g_tile, 1);
        __syncthreads();
        int tile = s_tile;
        if (tile >= NTILES) break;
        int tileM = tile * 64;

        const __nv_bfloat16* pAh = g_Ahi + (size_t)(tileM + arow) * KTOT + seg * 8;
        const __nv_bfloat16* pAl = g_Alo + (size_t)(tileM + arow) * KTOT + seg * 8;

        float acc[2][4][4];
#pragma unroll
        for (int mf = 0; mf < 2; mf++)
#pragma unroll
            for (int nf = 0; nf < 4; nf++)
#pragma unroll
                for (int q = 0; q < 4; q++) acc[mf][nf][q] = 0.f;

        // prologue: stages 0 and 1 in flight
#pragma unroll
        for (int p = 0; p < 2; p++) {
            uint32_t sb = su + p * STAGE_BYTES;
            int koff = p * 32;
            cp16(sb + dA,                  pAh + koff);
            cp16(sb + SA_LO + dA,          pAl + koff);
            cp16(sb + dB0,                 pBh0 + koff);
            cp16(sb + dB1,                 pBh1 + koff);
            cp16(sb + SB_LO - SB_HI + dB0, pBl0 + koff);
            cp16(sb + SB_LO - SB_HI + dB1, pBl1 + koff);
            cp_commit();
        }

        int stg = 0;   // stage index of buffer being computed (0,1,2 cyclic)
#pragma unroll 1
        for (int it = 0; it < KSTAGES; it++) {
            if (it < KSTAGES - 1) cp_wait<1>(); else cp_wait<0>();
            __syncthreads();
            if (it + 2 < KSTAGES) {
                int pst = stg + 2; if (pst >= 3) pst -= 3;
                uint32_t sb = su + pst * STAGE_BYTES;
                int koff = (it + 2) * 32;
                cp16(sb + dA,                  pAh + koff);
                cp16(sb + SA_LO + dA,          pAl + koff);
                cp16(sb + dB0,                 pBh0 + koff);
                cp16(sb + dB1,                 pBh1 + koff);
                cp16(sb + SB_LO - SB_HI + dB0, pBl0 + koff);
                cp16(sb + SB_LO - SB_HI + dB1, pBl1 + koff);
                cp_commit();
            }

            uint32_t sb = su + stg * STAGE_BYTES;
#pragma unroll
            for (int ks = 0; ks < 2; ks++) {
                uint32_t ah[2][4], al[2][4], bh[4][2], bl[4][2];
                ldx4(ah[0], sb + aoff[0] + ks * 32);
                ldx4(ah[1], sb + aoff[1] + ks * 32);
                ldx4(al[0], sb + SA_LO + aoff[0] + ks * 32);
                ldx4(al[1], sb + SA_LO + aoff[1] + ks * 32);
                {
                    uint32_t r[4];
                    ldx4(r, sb + boff[0] + ks * 32);
                    bh[0][0] = r[0]; bh[0][1] = r[1]; bh[1][0] = r[2]; bh[1][1] = r[3];
                    ldx4(r, sb + boff[1] + ks * 32);
                    bh[2][0] = r[0]; bh[2][1] = r[1]; bh[3][0] = r[2]; bh[3][1] = r[3];
                    ldx4(r, sb + (SB_LO - SB_HI) + boff[0] + ks * 32);
                    bl[0][0] = r[0]; bl[0][1] = r[1]; bl[1][0] = r[2]; bl[1][1] = r[3];
                    ldx4(r, sb + (SB_LO - SB_HI) + boff[1] + ks * 32);
                    bl[2][0] = r[0]; bl[2][1] = r[1]; bl[3][0] = r[2]; bl[3][1] = r[3];
                }
                // product-major: same-acc reuse distance = 8 MMAs
#pragma unroll
                for (int mf = 0; mf < 2; mf++)
#pragma unroll
                    for (int nf = 0; nf < 4; nf++)
                        mma_bf16(acc[mf][nf], ah[mf], bh[nf]);
#pragma unroll
                for (int mf = 0; mf < 2; mf++)
#pragma unroll
                    for (int nf = 0; nf < 4; nf++)
                        mma_bf16(acc[mf][nf], ah[mf], bl[nf]);
#pragma unroll
                for (int mf = 0; mf < 2; mf++)
#pragma unroll
                    for (int nf = 0; nf < 4; nf++)
                        mma_bf16(acc[mf][nf], al[mf], bh[nf]);
            }
            if (++stg == 3) stg = 0;
        }

        // epilogue: bias + relu + store
#pragma unroll
        for (int mf = 0; mf < 2; mf++) {
#pragma unroll
            for (int nf = 0; nf < 4; nf++) {
                int col = wn + nf * 8 + 2 * (l & 3);
                float b0 = bias[col], b1 = bias[col + 1];
                int r0 = tileM + wm + mf * 16 + (l >> 2);
                int r1 = r0 + 8;
                if (r0 < NNODES) {
                    float2 o;
                    o.x = fmaxf(acc[mf][nf][0] + b0, 0.f);
                    o.y = fmaxf(acc[mf][nf][1] + b1, 0.f);
                    *(float2*)(out + (size_t)r0 * DIN + col) = o;
                }
                if (r1 < NNODES) {
                    float2 o;
                    o.x = fmaxf(acc[mf][nf][2] + b0, 0.f);
                    o.y = fmaxf(acc[mf][nf][3] + b1, 0.f);
                    *(float2*)(out + (size_t)r1 * DIN + col) = o;
                }
            }
        }
    }
}

// ---------------- launch ----------------

extern "C" void kernel_launch(void* const* d_in, const int* in_sizes, int n_in,
                              void* d_out, int out_size) {
    const float* x      = (const float*)d_in[0];
    const float* weight = (const float*)d_in[1];
    const float* wcomp  = (const float*)d_in[2];
    const float* bias   = (const float*)d_in[3];
    const float* loopw  = (const float*)d_in[4];
    const float* norm   = (const float*)d_in[5];
    const int*   src    = (const int*)d_in[6];
    const int*   dst    = (const int*)d_in[7];
    const int*   et     = (const int*)d_in[8];
    float* out = (float*)d_out;

    int E = in_sizes[6];

    cudaFuncSetAttribute(k_gemm_mma, cudaFuncAttributeMaxDynamicSharedMemorySize,
                         SMEM_TOTAL);

    k_histscan<<<(E + 255) / 256, 256>>>(dst, E, weight, loopw);
    k_scatter<<<(E + 255) / 256, 256>>>(dst, src, et, norm, E);
    k_edge<<<EDGE_GRID, 128>>>(x, wcomp);
    k_gemm_mma<<<GEMM_GRID, 256, SMEM_TOTAL>>>(bias, out);
}

// round 7
// speedup vs baseline: 6.2412x; 1.4460x over previous
#include <cuda_runtime.h>
#include <cuda_fp16.h>
#include <cstdint>

#define NNODES 20000
#define NEDGES 640000
#define RREL 64
#define BBASIS 16
#define DIN 128
#define KG 2048
#define KTOT 2176
#define AROWS 20096          /* padded; pad rows stay zero forever */
#define NTILES 313           /* ceil(20000/64) */
#define GEMM_GRID 444
#define EDGE_GRID 1184
#define KSTAGES 68           /* 2176 / 32 */

/* smem stage layout (bytes), 80B row stride keeps ldmatrix conflict-free */
#define SA 0
#define SB 5120
#define STAGE_BYTES 15360
#define NSTAGE 4
#define SMEM_TOTAL (NSTAGE * STAGE_BYTES)

typedef unsigned long long ull;

// ---------------- helpers ----------------

__device__ __forceinline__ ull f2fma(ull a, ull b, ull c) {
    ull d; asm("fma.rn.f32x2 %0, %1, %2, %3;" : "=l"(d) : "l"(a), "l"(b), "l"(c)); return d;
}
__device__ __forceinline__ ull f2dup(float v) {
    ull d; asm("mov.b64 %0, {%1, %1};" : "=l"(d) : "f"(v)); return d;
}
__device__ __forceinline__ float f2lo(ull v){ return __uint_as_float((unsigned)v); }
__device__ __forceinline__ float f2hi(ull v){ return __uint_as_float((unsigned)(v >> 32)); }

union F4U2 { float4 f4; ull u[2]; };

__device__ __forceinline__ uint32_t smem_u32(const void* p) {
    uint32_t a;
    asm("{ .reg .u64 t; cvta.to.shared.u64 t, %1; cvt.u32.u64 %0, t; }" : "=r"(a) : "l"(p));
    return a;
}

__device__ __forceinline__ void cp16(uint32_t dst, const void* src) {
    asm volatile("cp.async.cg.shared.global [%0], [%1], 16;" :: "r"(dst), "l"(src) : "memory");
}
__device__ __forceinline__ void cp_commit() {
    asm volatile("cp.async.commit_group;" ::: "memory");
}
template <int N>
__device__ __forceinline__ void cp_wait() {
    asm volatile("cp.async.wait_group %0;" :: "n"(N) : "memory");
}

__device__ __forceinline__ void ldx4(uint32_t* r, uint32_t addr) {
    asm volatile("ldmatrix.sync.aligned.m8n8.x4.shared.b16 {%0,%1,%2,%3}, [%4];"
        : "=r"(r[0]), "=r"(r[1]), "=r"(r[2]), "=r"(r[3]) : "r"(addr));
}

__device__ __forceinline__ void mma_fp16(float* d, const uint32_t* a, const uint32_t* b) {
    asm volatile(
        "mma.sync.aligned.m16n8k16.row.col.f32.f16.f16.f32 "
        "{%0,%1,%2,%3}, {%4,%5,%6,%7}, {%8,%9}, {%0,%1,%2,%3};"
        : "+f"(d[0]), "+f"(d[1]), "+f"(d[2]), "+f"(d[3])
        : "r"(a[0]), "r"(a[1]), "r"(a[2]), "r"(a[3]), "r"(b[0]), "r"(b[1]));
}

// ---------------- scratch ----------------
__device__ __half g_Ah[(size_t)AROWS * KTOT];
__device__ __half g_Wh[(size_t)DIN * KTOT];   // [n][k]
__device__ int g_cnt[NNODES];
__device__ int g_cur[NNODES];
__device__ int g_off[NNODES + 1];
__device__ uint2 g_edata[NEDGES];    // sorted packed: {src | et<<16, norm bits}
__device__ int g_tile;
__device__ int g_done;

// ---------------- hist + weight conversion + last-block scan ----------------

__global__ void k_histscan(const int* __restrict__ dst, int e,
                           const float* __restrict__ weight,
                           const float* __restrict__ loopw) {
    int i = blockIdx.x * blockDim.x + threadIdx.x;
    if (i < e) atomicAdd(&g_cnt[dst[i]], 1);
    if (i < DIN * KTOT) {
        int n = i & 127;
        int k = i >> 7;
        float w = (k < KG) ? weight[(size_t)k * 128 + n]
                           : loopw[(size_t)(k - KG) * 128 + n];
        g_Wh[(size_t)n * KTOT + k] = __float2half_rn(w);
    }
    __threadfence();
    __shared__ int s_last;
    if (threadIdx.x == 0) s_last = atomicAdd(&g_done, 1);
    __syncthreads();
    if (s_last == (int)gridDim.x - 1) {
        __shared__ int part[256];
        int t = threadIdx.x;
        const int chunk = 79;
        int base = t * chunk;
        int s = 0;
        for (int j = 0; j < chunk; j++) {
            int idx = base + j;
            if (idx < NNODES) s += g_cnt[idx];
        }
        part[t] = s;
        __syncthreads();
        for (int d = 1; d < 256; d <<= 1) {
            int v = (t >= d) ? part[t - d] : 0;
            __syncthreads();
            part[t] += v;
            __syncthreads();
        }
        int run = (t == 0) ? 0 : part[t - 1];
        for (int j = 0; j < chunk; j++) {
            int idx = base + j;
            if (idx < NNODES) { g_off[idx] = run; run += g_cnt[idx]; }
        }
        if (t == 255) g_off[NNODES] = run;
        if (t == 0) { g_done = 0; g_tile = 0; }
    }
}

__global__ void k_scatter(const int* __restrict__ dst, const int* __restrict__ src,
                          const int* __restrict__ et, const float* __restrict__ norm,
                          int e) {
    int i = blockIdx.x * blockDim.x + threadIdx.x;
    if (i < e) {
        int d = dst[i];
        int p = g_off[d] + atomicAdd(&g_cur[d], 1);
        g_edata[p] = make_uint2((uint32_t)src[i] | ((uint32_t)et[i] << 16),
                                __float_as_uint(norm[i]));
    }
}

// ---------------- edge accumulation (persistent, sequential edge stream) ----------------

__global__ void __launch_bounds__(128) k_edge(
    const float* __restrict__ x, const float* __restrict__ wcomp)
{
    __shared__ float4 wc_s[RREL * 4];
    int t = threadIdx.x;
    const float4* wcv = (const float4*)wcomp;
    wc_s[t]       = wcv[t];
    wc_s[t + 128] = wcv[t + 128];
    __syncthreads();

    for (int d = blockIdx.x; d < NNODES; d += gridDim.x) {
        ull acc[8];
#pragma unroll
        for (int j = 0; j < 8; j++) acc[j] = 0ull;

        int k0 = g_off[d], k1 = g_off[d + 1];
        int k = k0;
        for (; k + 4 <= k1; k += 4) {
            uint2 e0 = g_edata[k], e1 = g_edata[k + 1];
            uint2 e2 = g_edata[k + 2], e3 = g_edata[k + 3];
            int s0 = e0.x & 0xFFFF, s1 = e1.x & 0xFFFF;
            int s2 = e2.x & 0xFFFF, s3 = e3.x & 0xFFFF;
            float xv0 = __ldg(x + (size_t)s0 * DIN + t);
            float xv1 = __ldg(x + (size_t)s1 * DIN + t);
            float xv2 = __ldg(x + (size_t)s2 * DIN + t);
            float xv3 = __ldg(x + (size_t)s3 * DIN + t);
            xv0 *= __uint_as_float(e0.y);
            xv1 *= __uint_as_float(e1.y);
            xv2 *= __uint_as_float(e2.y);
            xv3 *= __uint_as_float(e3.y);
            ull xd0 = f2dup(xv0), xd1 = f2dup(xv1);
            ull xd2 = f2dup(xv2), xd3 = f2dup(xv3);
            const float4* wr0 = &wc_s[(e0.x >> 16) << 2];
            const float4* wr1 = &wc_s[(e1.x >> 16) << 2];
            const float4* wr2 = &wc_s[(e2.x >> 16) << 2];
            const float4* wr3 = &wc_s[(e3.x >> 16) << 2];
            F4U2 w;
#pragma unroll
            for (int j = 0; j < 4; j++) {
                w.f4 = wr0[j];
                acc[2 * j]     = f2fma(w.u[0], xd0, acc[2 * j]);
                acc[2 * j + 1] = f2fma(w.u[1], xd0, acc[2 * j + 1]);
            }
#pragma unroll
            for (int j = 0; j < 4; j++) {
                w.f4 = wr1[j];
                acc[2 * j]     = f2fma(w.u[0], xd1, acc[2 * j]);
                acc[2 * j + 1] = f2fma(w.u[1], xd1, acc[2 * j + 1]);
            }
#pragma unroll
            for (int j = 0; j < 4; j++) {
                w.f4 = wr2[j];
                acc[2 * j]     = f2fma(w.u[0], xd2, acc[2 * j]);
                acc[2 * j + 1] = f2fma(w.u[1], xd2, acc[2 * j + 1]);
            }
#pragma unroll
            for (int j = 0; j < 4; j++) {
                w.f4 = wr3[j];
                acc[2 * j]     = f2fma(w.u[0], xd3, acc[2 * j]);
                acc[2 * j + 1] = f2fma(w.u[1], xd3, acc[2 * j + 1]);
            }
        }
        for (; k < k1; k++) {
            uint2 e0 = g_edata[k];
            int s0 = e0.x & 0xFFFF;
            float xv0 = __ldg(x + (size_t)s0 * DIN + t) * __uint_as_float(e0.y);
            ull xd0 = f2dup(xv0);
            const float4* wr0 = &wc_s[(e0.x >> 16) << 2];
            F4U2 w;
#pragma unroll
            for (int j = 0; j < 4; j++) {
                w.f4 = wr0[j];
                acc[2 * j]     = f2fma(w.u[0], xd0, acc[2 * j]);
                acc[2 * j + 1] = f2fma(w.u[1], xd0, acc[2 * j + 1]);
            }
        }

        size_t base = (size_t)d * KTOT;
#pragma unroll
        for (int j = 0; j < 8; j++) {
            g_Ah[base + (2 * j) * DIN + t]     = __float2half_rn(f2lo(acc[j]));
            g_Ah[base + (2 * j + 1) * DIN + t] = __float2half_rn(f2hi(acc[j]));
        }
        g_Ah[base + KG + t] = __float2half_rn(__ldg(x + (size_t)d * DIN + t));
    }
}

// ---------------- single-product fp16 mma GEMM, 4-stage pipeline ----------------
// out = relu(A @ W^T + bias), A fp16, W fp16, fp32 accum.
// BM=64, BN=128, BK=32; 8 warps as 2m x 4n (warp tile 32x32). 3 CTAs/SM.

extern __shared__ char dynsmem[];

__global__ void __launch_bounds__(256, 3) k_gemm_mma(const float* __restrict__ bias,
                                                     float* __restrict__ out)
{
    __shared__ int s_tile;
    int t = threadIdx.x;
    int l = t & 31, wid = t >> 5;

    // re-zero sort counters for next graph replay
    int gid = blockIdx.x * 256 + t;
    if (gid < NNODES) { g_cnt[gid] = 0; g_cur[gid] = 0; }

    uint32_t su = smem_u32(dynsmem);

    int wm = (wid & 1) * 32;
    int wn = (wid >> 1) * 32;

    uint32_t aoff[2], boff[2];
#pragma unroll
    for (int mf = 0; mf < 2; mf++)
        aoff[mf] = (uint32_t)(SA + (wm + mf * 16 + (l & 15)) * 80 + (l >> 4) * 16);
#pragma unroll
    for (int nb = 0; nb < 2; nb++)
        boff[nb] = (uint32_t)(SB + (wn + nb * 16 + ((l >> 4) << 3) + (l & 7)) * 80
                              + ((l >> 3) & 1) * 16);

    // staging maps: A one cp16/thread, B two cp16/thread
    int arow = t >> 2;                // 0..63
    int aseg = t & 3;                 // 16B segment (8 halves)
    int brow = t >> 1;                // 0..127
    int bseg = (t & 1) * 2;           // segments bseg, bseg+1
    uint32_t dA  = (uint32_t)(SA + arow * 80 + aseg * 16);
    uint32_t dB0 = (uint32_t)(SB + brow * 80 + bseg * 16);
    uint32_t dB1 = dB0 + 16;
    const __half* pB0 = g_Wh + (size_t)brow * KTOT + bseg * 8;
    const __half* pB1 = pB0 + 8;

    for (;;) {
        __syncthreads();
        if (t == 0) s_tile = atomicAdd(&g_tile, 1);
        __syncthreads();
        int tile = s_tile;
        if (tile >= NTILES) break;
        int tileM = tile * 64;

        const __half* pA = g_Ah + (size_t)(tileM + arow) * KTOT + aseg * 8;

        float acc[2][4][4];
#pragma unroll
        for (int mf = 0; mf < 2; mf++)
#pragma unroll
            for (int nf = 0; nf < 4; nf++)
#pragma unroll
                for (int q = 0; q < 4; q++) acc[mf][nf][q] = 0.f;

        // prologue: stages 0..2 in flight
#pragma unroll
        for (int p = 0; p < 3; p++) {
            uint32_t sb = su + p * STAGE_BYTES;
            int koff = p * 32;
            cp16(sb + dA,  pA  + koff);
            cp16(sb + dB0, pB0 + koff);
            cp16(sb + dB1, pB1 + koff);
            cp_commit();
        }

        int stg = 0;
#pragma unroll 1
        for (int it = 0; it < KSTAGES; it++) {
            cp_wait<2>();
            __syncthreads();
            if (it + 3 < KSTAGES) {
                int pst = stg + 3; if (pst >= NSTAGE) pst -= NSTAGE;
                uint32_t sb = su + pst * STAGE_BYTES;
                int koff = (it + 3) * 32;
                cp16(sb + dA,  pA  + koff);
                cp16(sb + dB0, pB0 + koff);
                cp16(sb + dB1, pB1 + koff);
            }
            cp_commit();

            uint32_t sb = su + stg * STAGE_BYTES;
#pragma unroll
            for (int ks = 0; ks < 2; ks++) {
                uint32_t ah[2][4], bh[4][2];
                ldx4(ah[0], sb + aoff[0] + ks * 32);
                ldx4(ah[1], sb + aoff[1] + ks * 32);
                {
                    uint32_t r[4];
                    ldx4(r, sb + boff[0] + ks * 32);
                    bh[0][0] = r[0]; bh[0][1] = r[1]; bh[1][0] = r[2]; bh[1][1] = r[3];
                    ldx4(r, sb + boff[1] + ks * 32);
                    bh[2][0] = r[0]; bh[2][1] = r[1]; bh[3][0] = r[2]; bh[3][1] = r[3];
                }
#pragma unroll
                for (int mf = 0; mf < 2; mf++)
#pragma unroll
                    for (int nf = 0; nf < 4; nf++)
                        mma_fp16(acc[mf][nf], ah[mf], bh[nf]);
            }
            if (++stg == NSTAGE) stg = 0;
        }

        // epilogue: bias + relu + store
#pragma unroll
        for (int mf = 0; mf < 2; mf++) {
#pragma unroll
            for (int nf = 0; nf < 4; nf++) {
                int col = wn + nf * 8 + 2 * (l & 3);
                float b0 = bias[col], b1 = bias[col + 1];
                int r0 = tileM + wm + mf * 16 + (l >> 2);
                int r1 = r0 + 8;
                if (r0 < NNODES) {
                    float2 o;
                    o.x = fmaxf(acc[mf][nf][0] + b0, 0.f);
                    o.y = fmaxf(acc[mf][nf][1] + b1, 0.f);
                    *(float2*)(out + (size_t)r0 * DIN + col) = o;
                }
                if (r1 < NNODES) {
                    float2 o;
                    o.x = fmaxf(acc[mf][nf][2] + b0, 0.f);
                    o.y = fmaxf(acc[mf][nf][3] + b1, 0.f);
                    *(float2*)(out + (size_t)r1 * DIN + col) = o;
                }
            }
        }
    }
}

// ---------------- launch ----------------

extern "C" void kernel_launch(void* const* d_in, const int* in_sizes, int n_in,
                              void* d_out, int out_size) {
    const float* x      = (const float*)d_in[0];
    const float* weight = (const float*)d_in[1];
    const float* wcomp  = (const float*)d_in[2];
    const float* bias   = (const float*)d_in[3];
    const float* loopw  = (const float*)d_in[4];
    const float* norm   = (const float*)d_in[5];
    const int*   src    = (const int*)d_in[6];
    const int*   dst    = (const int*)d_in[7];
    const int*   et     = (const int*)d_in[8];
    float* out = (float*)d_out;

    int E = in_sizes[6];

    cudaFuncSetAttribute(k_gemm_mma, cudaFuncAttributeMaxDynamicSharedMemorySize,
                         SMEM_TOTAL);

    k_histscan<<<(E + 255) / 256, 256>>>(dst, E, weight, loopw);
    k_scatter<<<(E + 255) / 256, 256>>>(dst, src, et, norm, E);
    k_edge<<<EDGE_GRID, 128>>>(x, wcomp);
    k_gemm_mma<<<GEMM_GRID, 256, SMEM_TOTAL>>>(bias, out);
}

// round 8
// speedup vs baseline: 7.1505x; 1.1457x over previous
#include <cuda_runtime.h>
#include <cuda_fp16.h>
#include <cstdint>

#define NNODES 20000
#define NEDGES 640000
#define RREL 64
#define BBASIS 16
#define DIN 128
#define KG 2048
#define KTOT 2176
#define AROWS 20096          /* padded; pad rows stay zero forever */
#define NTILES 313           /* ceil(20000/64) */
#define GEMM_GRID 444
#define EDGE_GRID 740
#define KSTAGES 68           /* 2176 / 32 */

/* GEMM smem stage layout (bytes), 80B row stride keeps ldmatrix conflict-free */
#define SA 0
#define SB 5120
#define STAGE_BYTES 15360
#define NSTAGE 4
#define SMEM_TOTAL (NSTAGE * STAGE_BYTES)

/* edge kernel smem strides */
#define XS_STRIDE 272        /* 256B row + 16B pad: LDSM phases hit all 32 banks */
#define AT_STRIDE 48         /* 32B row + 16B pad: conflict-free */

typedef unsigned long long ull;

// ---------------- helpers ----------------

__device__ __forceinline__ uint32_t smem_u32(const void* p) {
    uint32_t a;
    asm("{ .reg .u64 t; cvta.to.shared.u64 t, %1; cvt.u32.u64 %0, t; }" : "=r"(a) : "l"(p));
    return a;
}

__device__ __forceinline__ void cp16(uint32_t dst, const void* src) {
    asm volatile("cp.async.cg.shared.global [%0], [%1], 16;" :: "r"(dst), "l"(src) : "memory");
}
__device__ __forceinline__ void cp_commit() {
    asm volatile("cp.async.commit_group;" ::: "memory");
}
template <int N>
__device__ __forceinline__ void cp_wait() {
    asm volatile("cp.async.wait_group %0;" :: "n"(N) : "memory");
}

__device__ __forceinline__ void ldx4(uint32_t* r, uint32_t addr) {
    asm volatile("ldmatrix.sync.aligned.m8n8.x4.shared.b16 {%0,%1,%2,%3}, [%4];"
        : "=r"(r[0]), "=r"(r[1]), "=r"(r[2]), "=r"(r[3]) : "r"(addr));
}
__device__ __forceinline__ void ldx4t(uint32_t* r, uint32_t addr) {
    asm volatile("ldmatrix.sync.aligned.m8n8.x4.trans.shared.b16 {%0,%1,%2,%3}, [%4];"
        : "=r"(r[0]), "=r"(r[1]), "=r"(r[2]), "=r"(r[3]) : "r"(addr));
}

__device__ __forceinline__ void mma_fp16(float* d, const uint32_t* a, const uint32_t* b) {
    asm volatile(
        "mma.sync.aligned.m16n8k16.row.col.f32.f16.f16.f32 "
        "{%0,%1,%2,%3}, {%4,%5,%6,%7}, {%8,%9}, {%0,%1,%2,%3};"
        : "+f"(d[0]), "+f"(d[1]), "+f"(d[2]), "+f"(d[3])
        : "r"(a[0]), "r"(a[1]), "r"(a[2]), "r"(a[3]), "r"(b[0]), "r"(b[1]));
}

// ---------------- scratch ----------------
__device__ __half g_Ah[(size_t)AROWS * KTOT];
__device__ __half g_Wh[(size_t)DIN * KTOT];   // [n][k]
__device__ __half g_xh[(size_t)NNODES * DIN]; // x in fp16
__device__ int g_cnt[NNODES];
__device__ int g_cur[NNODES];
__device__ int g_off[NNODES + 1];
__device__ uint2 g_edata[NEDGES];    // sorted packed: {src | et<<16, norm bits}
__device__ int g_tile;
__device__ int g_node;
__device__ int g_done;

// ---------------- hist + weight/x conversion + last-block scan ----------------

__global__ void k_histscan(const int* __restrict__ dst, int e,
                           const float* __restrict__ weight,
                           const float* __restrict__ loopw,
                           const float* __restrict__ x) {
    int i = blockIdx.x * blockDim.x + threadIdx.x;
    int nthreads = gridDim.x * blockDim.x;
    if (i < e) atomicAdd(&g_cnt[dst[i]], 1);
    if (i < DIN * KTOT) {
        int n = i & 127;
        int k = i >> 7;
        float w = (k < KG) ? weight[(size_t)k * 128 + n]
                           : loopw[(size_t)(k - KG) * 128 + n];
        g_Wh[(size_t)n * KTOT + k] = __float2half_rn(w);
    }
    // x -> fp16
    for (int j = i; j < NNODES * DIN / 2; j += nthreads) {
        float2 v = ((const float2*)x)[j];
        ((__half2*)g_xh)[j] = __floats2half2_rn(v.x, v.y);
    }
    __threadfence();
    __shared__ int s_last;
    if (threadIdx.x == 0) s_last = atomicAdd(&g_done, 1);
    __syncthreads();
    if (s_last == (int)gridDim.x - 1) {
        __shared__ int part[256];
        int t = threadIdx.x;
        const int chunk = 79;
        int base = t * chunk;
        int s = 0;
        for (int j = 0; j < chunk; j++) {
            int idx = base + j;
            if (idx < NNODES) s += g_cnt[idx];
        }
        part[t] = s;
        __syncthreads();
        for (int d = 1; d < 256; d <<= 1) {
            int v = (t >= d) ? part[t - d] : 0;
            __syncthreads();
            part[t] += v;
            __syncthreads();
        }
        int run = (t == 0) ? 0 : part[t - 1];
        for (int j = 0; j < chunk; j++) {
            int idx = base + j;
            if (idx < NNODES) { g_off[idx] = run; run += g_cnt[idx]; }
        }
        if (t == 255) g_off[NNODES] = run;
        if (t == 0) { g_done = 0; g_tile = 0; g_node = 0; }
    }
}

__global__ void k_scatter(const int* __restrict__ dst, const int* __restrict__ src,
                          const int* __restrict__ et, const float* __restrict__ norm,
                          int e) {
    int i = blockIdx.x * blockDim.x + threadIdx.x;
    if (i < e) {
        int d = dst[i];
        int p = g_off[d] + atomicAdd(&g_cur[d], 1);
        g_edata[p] = make_uint2((uint32_t)src[i] | ((uint32_t)et[i] << 16),
                                __float_as_uint(norm[i]));
    }
}

// ---------------- tensor-core edge accumulation ----------------
// Per dst node: G[16,128] = A[16,deg] @ Xs[deg,128] via m16n8k16 chunks of 16
// edges. A[b,e] = w_comp[et_e,b] * norm_e (fp16, built in smem, zero rows for
// tail). Xs[e,:] = x_fp16[src_e,:] gathered via cp.async. Warp w owns cols
// 16w..16w+15 (2 n-tiles). Double-buffered, 1 syncthreads per chunk.

__global__ void __launch_bounds__(256) k_edge_tc(const float* __restrict__ wcomp)
{
    __shared__ float wc_s[RREL * BBASIS];                     // 4KB fp32 LUT
    __shared__ __align__(16) char XS[2][16 * XS_STRIDE];      // 8704B
    __shared__ __align__(16) char AT[2][16 * AT_STRIDE];      // 1536B
    __shared__ int s_node;

    int t = threadIdx.x;
    int l = t & 31, w = t >> 5;

    for (int i = t; i < RREL * BBASIS; i += 256) wc_s[i] = wcomp[i];
    const float4* wc4 = (const float4*)wc_s;

    int eidx = t >> 4;        // edge slot 0..15
    int seg  = t & 15;        // 16B segment within 256B row
    bool abuild = (eidx == seg);   // 16 threads, one per edge slot

    uint32_t xs_base[2] = { smem_u32(XS[0]), smem_u32(XS[1]) };
    uint32_t at_base[2] = { smem_u32(AT[0]), smem_u32(AT[1]) };
    uint32_t xs_dst[2] = { xs_base[0] + eidx * XS_STRIDE + seg * 16,
                           xs_base[1] + eidx * XS_STRIDE + seg * 16 };

    // ldmatrix lane addresses
    uint32_t a_off = (uint32_t)(((l & 7) + ((l >> 4) & 1) * 8) * AT_STRIDE
                                + ((l >> 3) & 1) * 16);
    uint32_t b_off = (uint32_t)((l & 15) * XS_STRIDE + 32 * w + ((l >> 4) & 1) * 16);

    for (;;) {
        __syncthreads();                 // also protects buffers across nodes
        if (t == 0) s_node = atomicAdd(&g_node, 1);
        __syncthreads();
        int d = s_node;
        if (d >= NNODES) break;

        int k0 = g_off[d], k1 = g_off[d + 1];
        int deg = k1 - k0;
        int nch = (deg + 15) >> 4;

        float acc[2][4];
#pragma unroll
        for (int j = 0; j < 2; j++)
#pragma unroll
            for (int q = 0; q < 4; q++) acc[j][q] = 0.f;

        if (nch > 0) {
            // ---- prologue: stage chunk 0 into buf 0 ----
            {
                int kk = k0 + eidx;
                uint2 en = __ldg(&g_edata[min(kk, k1 - 1)]);
                bool v = kk < k1;
                int s = en.x & 0xFFFF;
                cp16(xs_dst[0], g_xh + (size_t)s * DIN + seg * 8);
                if (abuild) {
                    float nv = v ? __uint_as_float(en.y) : 0.f;
                    int r = en.x >> 16;
                    float4 w0 = wc4[r * 4 + 0], w1 = wc4[r * 4 + 1];
                    float4 w2 = wc4[r * 4 + 2], w3 = wc4[r * 4 + 3];
                    __half2 h[8];
                    h[0] = __floats2half2_rn(w0.x * nv, w0.y * nv);
                    h[1] = __floats2half2_rn(w0.z * nv, w0.w * nv);
                    h[2] = __floats2half2_rn(w1.x * nv, w1.y * nv);
                    h[3] = __floats2half2_rn(w1.z * nv, w1.w * nv);
                    h[4] = __floats2half2_rn(w2.x * nv, w2.y * nv);
                    h[5] = __floats2half2_rn(w2.z * nv, w2.w * nv);
                    h[6] = __floats2half2_rn(w3.x * nv, w3.y * nv);
                    h[7] = __floats2half2_rn(w3.z * nv, w3.w * nv);
                    *(uint4*)(AT[0] + eidx * AT_STRIDE)      = *(uint4*)&h[0];
                    *(uint4*)(AT[0] + eidx * AT_STRIDE + 16) = *(uint4*)&h[4];
                }
                cp_commit();
            }

#pragma unroll 1
            for (int c = 0; c < nch; c++) {
                // prefetch next chunk's edge record (LDG overlaps wait+sync)
                uint2 en; bool vn = false; bool have = (c + 1 < nch);
                int nbuf = (c + 1) & 1;
                if (have) {
                    int kk = k0 + (c + 1) * 16 + eidx;
                    vn = kk < k1;
                    en = __ldg(&g_edata[min(kk, k1 - 1)]);
                }
                cp_wait<0>();
                __syncthreads();         // chunk c data visible; prev MMA done
                if (have) {
                    int s = en.x & 0xFFFF;
                    cp16(xs_dst[nbuf], g_xh + (size_t)s * DIN + seg * 8);
                    if (abuild) {
                        float nv = vn ? __uint_as_float(en.y) : 0.f;
                        int r = en.x >> 16;
                        float4 w0 = wc4[r * 4 + 0], w1 = wc4[r * 4 + 1];
                        float4 w2 = wc4[r * 4 + 2], w3 = wc4[r * 4 + 3];
                        __half2 h[8];
                        h[0] = __floats2half2_rn(w0.x * nv, w0.y * nv);
                        h[1] = __floats2half2_rn(w0.z * nv, w0.w * nv);
                        h[2] = __floats2half2_rn(w1.x * nv, w1.y * nv);
                        h[3] = __floats2half2_rn(w1.z * nv, w1.w * nv);
                        h[4] = __floats2half2_rn(w2.x * nv, w2.y * nv);
                        h[5] = __floats2half2_rn(w2.z * nv, w2.w * nv);
                        h[6] = __floats2half2_rn(w3.x * nv, w3.y * nv);
                        h[7] = __floats2half2_rn(w3.z * nv, w3.w * nv);
                        *(uint4*)(AT[nbuf] + eidx * AT_STRIDE)      = *(uint4*)&h[0];
                        *(uint4*)(AT[nbuf] + eidx * AT_STRIDE + 16) = *(uint4*)&h[4];
                    }
                    cp_commit();
                }

                int buf = c & 1;
                uint32_t af[4], bf[4];
                ldx4t(af, at_base[buf] + a_off);
                ldx4t(bf, xs_base[buf] + b_off);
                mma_fp16(acc[0], af, &bf[0]);
                mma_fp16(acc[1], af, &bf[2]);
            }
        }

        // ---- epilogue: store G rows (bases) + self-loop ----
        size_t base = (size_t)d * KTOT;
        int row = l >> 2, cc = 2 * (l & 3);
#pragma unroll
        for (int j = 0; j < 2; j++) {
            int col = w * 16 + j * 8 + cc;
            __half2 h01 = __floats2half2_rn(acc[j][0], acc[j][1]);
            __half2 h23 = __floats2half2_rn(acc[j][2], acc[j][3]);
            *(__half2*)(g_Ah + base + (size_t)row * 128 + col)       = h01;
            *(__half2*)(g_Ah + base + (size_t)(row + 8) * 128 + col) = h23;
        }
        if (t < 64)
            ((uint32_t*)(g_Ah + base + KG))[t] =
                ((const uint32_t*)(g_xh + (size_t)d * DIN))[t];
    }
}

// ---------------- single-product fp16 mma GEMM, 4-stage pipeline ----------------
// out = relu(A @ W^T + bias), A fp16, W fp16, fp32 accum.
// BM=64, BN=128, BK=32; 8 warps as 2m x 4n (warp tile 32x32). 3 CTAs/SM.

extern __shared__ char dynsmem[];

__global__ void __launch_bounds__(256, 3) k_gemm_mma(const float* __restrict__ bias,
                                                     float* __restrict__ out)
{
    __shared__ int s_tile;
    int t = threadIdx.x;
    int l = t & 31, wid = t >> 5;

    // re-zero sort counters for next graph replay
    int gid = blockIdx.x * 256 + t;
    if (gid < NNODES) { g_cnt[gid] = 0; g_cur[gid] = 0; }

    uint32_t su = smem_u32(dynsmem);

    int wm = (wid & 1) * 32;
    int wn = (wid >> 1) * 32;

    uint32_t aoff[2], boff[2];
#pragma unroll
    for (int mf = 0; mf < 2; mf++)
        aoff[mf] = (uint32_t)(SA + (wm + mf * 16 + (l & 15)) * 80 + (l >> 4) * 16);
#pragma unroll
    for (int nb = 0; nb < 2; nb++)
        boff[nb] = (uint32_t)(SB + (wn + nb * 16 + ((l >> 4) << 3) + (l & 7)) * 80
                              + ((l >> 3) & 1) * 16);

    int arow = t >> 2;
    int aseg = t & 3;
    int brow = t >> 1;
    int bseg = (t & 1) * 2;
    uint32_t dA  = (uint32_t)(SA + arow * 80 + aseg * 16);
    uint32_t dB0 = (uint32_t)(SB + brow * 80 + bseg * 16);
    uint32_t dB1 = dB0 + 16;
    const __half* pB0 = g_Wh + (size_t)brow * KTOT + bseg * 8;
    const __half* pB1 = pB0 + 8;

    for (;;) {
        __syncthreads();
        if (t == 0) s_tile = atomicAdd(&g_tile, 1);
        __syncthreads();
        int tile = s_tile;
        if (tile >= NTILES) break;
        int tileM = tile * 64;

        const __half* pA = g_Ah + (size_t)(tileM + arow) * KTOT + aseg * 8;

        float acc[2][4][4];
#pragma unroll
        for (int mf = 0; mf < 2; mf++)
#pragma unroll
            for (int nf = 0; nf < 4; nf++)
#pragma unroll
                for (int q = 0; q < 4; q++) acc[mf][nf][q] = 0.f;

#pragma unroll
        for (int p = 0; p < 3; p++) {
            uint32_t sb = su + p * STAGE_BYTES;
            int koff = p * 32;
            cp16(sb + dA,  pA  + koff);
            cp16(sb + dB0, pB0 + koff);
            cp16(sb + dB1, pB1 + koff);
            cp_commit();
        }

        int stg = 0;
#pragma unroll 1
        for (int it = 0; it < KSTAGES; it++) {
            cp_wait<2>();
            __syncthreads();
            if (it + 3 < KSTAGES) {
                int pst = stg + 3; if (pst >= NSTAGE) pst -= NSTAGE;
                uint32_t sb = su + pst * STAGE_BYTES;
                int koff = (it + 3) * 32;
                cp16(sb + dA,  pA  + koff);
                cp16(sb + dB0, pB0 + koff);
                cp16(sb + dB1, pB1 + koff);
            }
            cp_commit();

            uint32_t sb = su + stg * STAGE_BYTES;
#pragma unroll
            for (int ks = 0; ks < 2; ks++) {
                uint32_t ah[2][4], bh[4][2];
                ldx4(ah[0], sb + aoff[0] + ks * 32);
                ldx4(ah[1], sb + aoff[1] + ks * 32);
                {
                    uint32_t r[4];
                    ldx4(r, sb + boff[0] + ks * 32);
                    bh[0][0] = r[0]; bh[0][1] = r[1]; bh[1][0] = r[2]; bh[1][1] = r[3];
                    ldx4(r, sb + boff[1] + ks * 32);
                    bh[2][0] = r[0]; bh[2][1] = r[1]; bh[3][0] = r[2]; bh[3][1] = r[3];
                }
#pragma unroll
                for (int mf = 0; mf < 2; mf++)
#pragma unroll
                    for (int nf = 0; nf < 4; nf++)
                        mma_fp16(acc[mf][nf], ah[mf], bh[nf]);
            }
            if (++stg == NSTAGE) stg = 0;
        }

#pragma unroll
        for (int mf = 0; mf < 2; mf++) {
#pragma unroll
            for (int nf = 0; nf < 4; nf++) {
                int col = wn + nf * 8 + 2 * (l & 3);
                float b0 = bias[col], b1 = bias[col + 1];
                int r0 = tileM + wm + mf * 16 + (l >> 2);
                int r1 = r0 + 8;
                if (r0 < NNODES) {
                    float2 o;
                    o.x = fmaxf(acc[mf][nf][0] + b0, 0.f);
                    o.y = fmaxf(acc[mf][nf][1] + b1, 0.f);
                    *(float2*)(out + (size_t)r0 * DIN + col) = o;
                }
                if (r1 < NNODES) {
                    float2 o;
                    o.x = fmaxf(acc[mf][nf][2] + b0, 0.f);
                    o.y = fmaxf(acc[mf][nf][3] + b1, 0.f);
                    *(float2*)(out + (size_t)r1 * DIN + col) = o;
                }
            }
        }
    }
}

// ---------------- launch ----------------

extern "C" void kernel_launch(void* const* d_in, const int* in_sizes, int n_in,
                              void* d_out, int out_size) {
    const float* x      = (const float*)d_in[0];
    const float* weight = (const float*)d_in[1];
    const float* wcomp  = (const float*)d_in[2];
    const float* bias   = (const float*)d_in[3];
    const float* loopw  = (const float*)d_in[4];
    const float* norm   = (const float*)d_in[5];
    const int*   src    = (const int*)d_in[6];
    const int*   dst    = (const int*)d_in[7];
    const int*   et     = (const int*)d_in[8];
    float* out = (float*)d_out;

    int E = in_sizes[6];

    cudaFuncSetAttribute(k_gemm_mma, cudaFuncAttributeMaxDynamicSharedMemorySize,
                         SMEM_TOTAL);

    k_histscan<<<(E + 255) / 256, 256>>>(dst, E, weight, loopw, x);
    k_scatter<<<(E + 255) / 256, 256>>>(dst, src, et, norm, E);
    k_edge_tc<<<EDGE_GRID, 256>>>(wcomp);
    k_gemm_mma<<<GEMM_GRID, 256, SMEM_TOTAL>>>(bias, out);
}